// round 14
// baseline (speedup 1.0000x reference)
#include <cuda_runtime.h>
#include <cstdint>
#include <math.h>

#define N_NODES 8192
#define DIM     512

// scratch (device globals: no allocation allowed)
__device__ float    g_n1[N_NODES * DIM];                  // 16 MB
__device__ float    g_n2[N_NODES * DIM];                  // 16 MB
__device__ unsigned g_pang[(size_t)N_NODES * N_NODES];    // 256 MB pang bits

// ---------------------------------------------------------------------------
// Bit-replication of XLA fast tanh f32 (verified bitmatch rounds 3-13).
// ---------------------------------------------------------------------------
__device__ __forceinline__ float xla_tanh(float x) {
    float ax = fabsf(x);
    float xc = fminf(fmaxf(x, -7.90531110763549805f), 7.90531110763549805f);
    float x2 = __fmul_rn(xc, xc);
    float p = -2.76076847742355e-16f;
    p = fmaf(p, x2,  2.00018790482477e-13f);
    p = fmaf(p, x2, -8.60467152213735e-11f);
    p = fmaf(p, x2,  5.12229709037114e-08f);
    p = fmaf(p, x2,  1.48572235717979e-05f);
    p = fmaf(p, x2,  6.37261928875436e-04f);
    p = fmaf(p, x2,  4.89352455891786e-03f);
    float q =  1.19825839466702e-06f;
    q = fmaf(q, x2,  1.18534705686654e-04f);
    q = fmaf(q, x2,  2.26843463243900e-03f);
    q = fmaf(q, x2,  4.89352518554385e-03f);
    float r = __fdiv_rn(__fmul_rn(xc, p), q);
    return (ax < 0.0004f) ? x : r;
}

__device__ __forceinline__ float tanh3_(float x) {
    return xla_tanh(__fmul_rn(3.0f, x));
}

// pang bits: exactly abs(adj + 0.01*noise) as rn mul + rn add (matches ref)
__device__ __forceinline__ unsigned pang_bits(float adj, float nz) {
    return __float_as_uint(fabsf(__fadd_rn(adj, __fmul_rn(0.01f, nz))));
}

// ---------------------------------------------------------------------------
// 8-k slab helpers (embed kernel, proven config). Buffers: [buf*1024+k*128+row]
// ---------------------------------------------------------------------------
__device__ __forceinline__ void stage_f(
    float* sA, float* sB, int buf,
    const float4 av, const float4 bv, int lrow, int lc)
{
    float* A = sA + buf * 1024;
    float* B = sB + buf * 1024;
    A[(lc + 0) * 128 + lrow] = av.x;  A[(lc + 1) * 128 + lrow] = av.y;
    A[(lc + 2) * 128 + lrow] = av.z;  A[(lc + 3) * 128 + lrow] = av.w;
    B[(lc + 0) * 128 + lrow] = bv.x;  B[(lc + 1) * 128 + lrow] = bv.y;
    B[(lc + 2) * 128 + lrow] = bv.z;  B[(lc + 3) * 128 + lrow] = bv.w;
}

__device__ __forceinline__ void compute_pk(
    const float* sA, const float* sB, int buf,
    int TX, int TY, unsigned long long (&acc2)[8][4])
{
    const float* A = sA + buf * 1024;
    const float* B = sB + buf * 1024;
#pragma unroll
    for (int k = 0; k < 8; ++k) {
        float a[8];
        *(float4*)&a[0] = *(const float4*)&A[k * 128 + TY * 8];
        *(float4*)&a[4] = *(const float4*)&A[k * 128 + TY * 8 + 4];
        unsigned long long b2[4];
        *(float4*)&b2[0] = *(const float4*)&B[k * 128 + TX * 8];
        *(float4*)&b2[2] = *(const float4*)&B[k * 128 + TX * 8 + 4];
#pragma unroll
        for (int r = 0; r < 8; ++r) {
            unsigned long long a2;
            asm("mov.b64 %0, {%1, %1};" : "=l"(a2) : "f"(a[r]));
#pragma unroll
            for (int c2 = 0; c2 < 4; ++c2)
                asm("fma.rn.f32x2 %0, %1, %2, %0;" : "+l"(acc2[r][c2]) : "l"(a2), "l"(b2[c2]));
        }
    }
}

__device__ __forceinline__ void gemm_tile_pk(
    const float* __restrict__ Ablk, const float* __restrict__ Bblk,
    float* sA, float* sB, int lrow, int lc, int TX, int TY,
    unsigned long long (&acc2)[8][4])
{
    const float* ap = Ablk + (size_t)lrow * DIM + lc;
    const float* bp = Bblk + (size_t)lrow * DIM + lc;

    float4 av = *(const float4*)ap; ap += 8;
    float4 bv = *(const float4*)bp; bp += 8;
    stage_f(sA, sB, 0, av, bv, lrow, lc);
    __syncthreads();

#pragma unroll 1
    for (int kt = 0; kt < DIM / 8; kt += 2) {
        av = *(const float4*)ap; bv = *(const float4*)bp; ap += 8; bp += 8;
        compute_pk(sA, sB, 0, TX, TY, acc2);
        stage_f(sA, sB, 1, av, bv, lrow, lc);
        __syncthreads();
        if (kt + 2 < DIM / 8) {
            av = *(const float4*)ap; bv = *(const float4*)bp; ap += 8; bp += 8;
        }
        compute_pk(sA, sB, 1, TX, TY, acc2);
        if (kt + 2 < DIM / 8) stage_f(sA, sB, 0, av, bv, lrow, lc);
        __syncthreads();
    }
}

// ---------------------------------------------------------------------------
// Kernel 1: both embeds via blockIdx.z; 128x128 FFMA2 tiles (proven, 227us)
// ---------------------------------------------------------------------------
__global__ __launch_bounds__(256) void embed_gemm(
    const float* __restrict__ emb1, const float* __restrict__ emb2,
    const float* __restrict__ W1,   const float* __restrict__ W2,
    const float* __restrict__ b1,   const float* __restrict__ b2,
    const int* __restrict__ idx)
{
    __shared__ __align__(16) float sA[2 * 1024];
    __shared__ __align__(16) float sB[2 * 1024];

    const int which = blockIdx.z;
    const float* __restrict__ emb  = which ? emb2 : emb1;
    const float* __restrict__ W    = which ? W2   : W1;
    const float* __restrict__ bias = which ? b2   : b1;
    float* __restrict__ dst        = which ? g_n2 : g_n1;

    const int bj = blockIdx.x, bi = blockIdx.y;
    const int tid = threadIdx.x;
    const int lrow = tid >> 1, lc = (tid & 1) * 4;
    const int tx = tid & 15, ty = tid >> 4;

    unsigned long long acc2[8][4];
#pragma unroll
    for (int r = 0; r < 8; ++r)
#pragma unroll
        for (int c2 = 0; c2 < 4; ++c2) acc2[r][c2] = 0ull;

    const int arow = idx[bi * 128 + lrow];   // gather
    const float* Ablk = emb + (size_t)arow * DIM - (size_t)lrow * DIM;
    const float* Bblk = W + (size_t)(bj * 128) * DIM;

    gemm_tile_pk(Ablk, Bblk, sA, sB, lrow, lc, tx, ty, acc2);

    const int gi0 = bi * 128 + ty * 8;
    const int gj0 = bj * 128 + tx * 8;
    float bb[8];
    *(float4*)&bb[0] = *(const float4*)&bias[gj0];
    *(float4*)&bb[4] = *(const float4*)&bias[gj0 + 4];
#pragma unroll
    for (int r = 0; r < 8; ++r) {
        float accf[8];
#pragma unroll
        for (int c2 = 0; c2 < 4; ++c2) {
            float2 t = *(float2*)&acc2[r][c2];
            accf[2 * c2] = t.x; accf[2 * c2 + 1] = t.y;
        }
        float v[8];
#pragma unroll
        for (int c = 0; c < 8; ++c)
            v[c] = tanh3_(__fadd_rn(accf[c], bb[c]));
        *(float4*)&dst[(size_t)(gi0 + r) * DIM + gj0]     = make_float4(v[0], v[1], v[2], v[3]);
        *(float4*)&dst[(size_t)(gi0 + r) * DIM + gj0 + 4] = make_float4(v[4], v[5], v[6], v[7]);
    }
}

// ---------------------------------------------------------------------------
// 16-k slab helpers (fused kernel). Buffers: [buf*2048 + k*128 + row]
// ---------------------------------------------------------------------------
__device__ __forceinline__ void stage16(
    float* sA, float* sB, int buf,
    const float4 av0, const float4 av1, const float4 bv0, const float4 bv1,
    int lrow, int lc)
{
    float* A = sA + buf * 2048;
    float* B = sB + buf * 2048;
    A[(lc + 0) * 128 + lrow] = av0.x;  A[(lc + 1) * 128 + lrow] = av0.y;
    A[(lc + 2) * 128 + lrow] = av0.z;  A[(lc + 3) * 128 + lrow] = av0.w;
    A[(lc + 8) * 128 + lrow] = av1.x;  A[(lc + 9) * 128 + lrow] = av1.y;
    A[(lc +10) * 128 + lrow] = av1.z;  A[(lc +11) * 128 + lrow] = av1.w;
    B[(lc + 0) * 128 + lrow] = bv0.x;  B[(lc + 1) * 128 + lrow] = bv0.y;
    B[(lc + 2) * 128 + lrow] = bv0.z;  B[(lc + 3) * 128 + lrow] = bv0.w;
    B[(lc + 8) * 128 + lrow] = bv1.x;  B[(lc + 9) * 128 + lrow] = bv1.y;
    B[(lc +10) * 128 + lrow] = bv1.z;  B[(lc +11) * 128 + lrow] = bv1.w;
}

__device__ __forceinline__ void compute16(
    const float* sA, const float* sB, int buf,
    int TX, int TY, unsigned long long (&acc2)[8][4])
{
    const float* A = sA + buf * 2048;
    const float* B = sB + buf * 2048;
#pragma unroll
    for (int k = 0; k < 16; ++k) {
        float a[8];
        *(float4*)&a[0] = *(const float4*)&A[k * 128 + TY * 8];
        *(float4*)&a[4] = *(const float4*)&A[k * 128 + TY * 8 + 4];
        unsigned long long b2[4];
        *(float4*)&b2[0] = *(const float4*)&B[k * 128 + TX * 8];
        *(float4*)&b2[2] = *(const float4*)&B[k * 128 + TX * 8 + 4];
#pragma unroll
        for (int r = 0; r < 8; ++r) {
            unsigned long long a2;
            asm("mov.b64 %0, {%1, %1};" : "=l"(a2) : "f"(a[r]));
#pragma unroll
            for (int c2 = 0; c2 < 4; ++c2)
                asm("fma.rn.f32x2 %0, %1, %2, %0;" : "+l"(acc2[r][c2]) : "l"(a2), "l"(b2[c2]));
        }
    }
}

__device__ __forceinline__ void gemm_tile16(
    const float* __restrict__ Ablk, const float* __restrict__ Bblk,
    float* sA, float* sB, int lrow, int lc, int TX, int TY,
    unsigned long long (&acc2)[8][4])
{
    const float* ap = Ablk + (size_t)lrow * DIM + lc;
    const float* bp = Bblk + (size_t)lrow * DIM + lc;

    float4 av0 = *(const float4*)ap, av1 = *(const float4*)(ap + 8); ap += 16;
    float4 bv0 = *(const float4*)bp, bv1 = *(const float4*)(bp + 8); bp += 16;
    stage16(sA, sB, 0, av0, av1, bv0, bv1, lrow, lc);
    __syncthreads();

#pragma unroll 1
    for (int kt = 0; kt < DIM / 16; kt += 2) {
        av0 = *(const float4*)ap; av1 = *(const float4*)(ap + 8); ap += 16;
        bv0 = *(const float4*)bp; bv1 = *(const float4*)(bp + 8); bp += 16;
        compute16(sA, sB, 0, TX, TY, acc2);
        stage16(sA, sB, 1, av0, av1, bv0, bv1, lrow, lc);
        __syncthreads();
        if (kt + 2 < DIM / 16) {
            av0 = *(const float4*)ap; av1 = *(const float4*)(ap + 8); ap += 16;
            bv0 = *(const float4*)bp; bv1 = *(const float4*)(bp + 8); bp += 16;
        }
        compute16(sA, sB, 1, TX, TY, acc2);
        if (kt + 2 < DIM / 16) stage16(sA, sB, 0, av0, av1, bv0, bv1, lrow, lc);
        __syncthreads();
    }
}

// ---------------------------------------------------------------------------
// Kernel 2 (fused): triangular tiles, diagonal-last. Writes adj to out AND
//   pang bits (|adj + 0.01*noise|) to g_pang — the noise read + pang store
//   ride under the FFMA-bound mainloop, so topk only has to stream pang.
// ---------------------------------------------------------------------------
__global__ __launch_bounds__(256, 2) void fused_adj_gemm(
    float* __restrict__ out, const float* __restrict__ noise)
{
    extern __shared__ __align__(16) float smem_dyn[];
    float* sA = smem_dyn;            // 2 * 2048 floats
    float* sB = sA + 2 * 2048;       // 2 * 2048 floats
    float* P  = sB + 2 * 2048;       // 16384 floats private stash: [e*1024 + tid*4]

    // tile decode with diagonal-last ordering
    const int t = blockIdx.x;
    int bi, bj;
    bool diag;
    if (t < 2016) {
        diag = false;
        int b = (int)((127.0 - sqrt(127.0 * 127.0 - 8.0 * (double)t)) * 0.5);
        if (b < 0) b = 0;
        if (b > 62) b = 62;
        while (b < 62 && ((b + 1) * 127 - (b + 1) * (b + 1)) / 2 <= t) ++b;
        while (b > 0 && (b * 127 - b * b) / 2 > t) --b;
        bi = b;
        bj = bi + 1 + (t - (bi * 127 - bi * bi) / 2);
    } else {
        diag = true;
        bi = bj = t - 2016;
    }

    const int tid = threadIdx.x;
    const int lrow = tid >> 1, lc = (tid & 1) * 4;
    const int tx = tid & 15, ty = tid >> 4;

    unsigned long long acc2[8][4];
#pragma unroll
    for (int r = 0; r < 8; ++r)
#pragma unroll
        for (int c2 = 0; c2 < 4; ++c2) acc2[r][c2] = 0ull;

    // Phase A, swapped roles (TX=ty, TY=tx): accA(r,c) = a1(bi: tx*8+r, bj: ty*8+c)
    gemm_tile16(g_n1 + (size_t)(bi * 128) * DIM, g_n2 + (size_t)(bj * 128) * DIM,
                sA, sB, lrow, lc, /*TX=*/ty, /*TY=*/tx, acc2);

    // stash accA: element (r,c) -> P[(2r + (c>>2))*1024 + tid*4 + (c&3)]
#pragma unroll
    for (int e = 0; e < 16; ++e) {
        const int r = e >> 1, c2 = (e & 1) * 2;
        float2 lo = *(float2*)&acc2[r][c2];
        float2 hi = *(float2*)&acc2[r][c2 + 1];
        *(float4*)&P[e * 1024 + tid * 4] = make_float4(lo.x, lo.y, hi.x, hi.y);
    }

    float B_[8][8];
    if (!diag) {
        // Phase B, normal roles: accB(r,c) = a1(bj: ty*8+r, bi: tx*8+c)
#pragma unroll
        for (int r = 0; r < 8; ++r)
#pragma unroll
            for (int c2 = 0; c2 < 4; ++c2) acc2[r][c2] = 0ull;
        gemm_tile16(g_n1 + (size_t)(bj * 128) * DIM, g_n2 + (size_t)(bi * 128) * DIM,
                    sA, sB, lrow, lc, tx, ty, acc2);
#pragma unroll
        for (int r = 0; r < 8; ++r)
#pragma unroll
            for (int c2 = 0; c2 < 4; ++c2) {
                float2 tt = *(float2*)&acc2[r][c2];
                B_[r][2 * c2] = tt.x; B_[r][2 * c2 + 1] = tt.y;
            }
        __syncthreads();
    } else {
        // diagonal: accB of thread (tx,ty) == accA of partner (ty,tx), bitwise
        __syncthreads();
        const int tid2 = (tid & 15) * 16 + (tid >> 4);
#pragma unroll
        for (int r = 0; r < 8; ++r)
#pragma unroll
            for (int c = 0; c < 8; ++c)
                B_[r][c] = P[(2 * r + (c >> 2)) * 1024 + tid2 * 4 + (c & 3)];
    }

    // tanh once, in place: B_[r][c] <- tanh3(accB(r,c) - accA(c,r))
#pragma unroll
    for (int c = 0; c < 8; ++c) {
        float rowA[8];
        *(float4*)&rowA[0] = *(const float4*)&P[(2 * c) * 1024 + tid * 4];
        *(float4*)&rowA[4] = *(const float4*)&P[(2 * c + 1) * 1024 + tid * 4];
#pragma unroll
        for (int r = 0; r < 8; ++r)
            B_[r][c] = tanh3_(__fsub_rn(B_[r][c], rowA[r]));
    }

    // Pass 1 — mirror tile (bi, bj): adj = -v; pang alongside (32B sectors)
    if (!diag) {
#pragma unroll
        for (int c = 0; c < 8; ++c) {
            size_t o = (size_t)(bi * 128 + tx * 8 + c) * N_NODES + bj * 128 + ty * 8;
            float4 nz0 = *(const float4*)&noise[o];
            float4 nz1 = *(const float4*)&noise[o + 4];
            float w[8];
#pragma unroll
            for (int r = 0; r < 8; ++r) w[r] = -B_[r][c];
            *(float4*)&out[o]     = make_float4(w[0], w[1], w[2], w[3]);
            *(float4*)&out[o + 4] = make_float4(w[4], w[5], w[6], w[7]);
            uint4 p0, p1;
            p0.x = pang_bits(w[0], nz0.x); p0.y = pang_bits(w[1], nz0.y);
            p0.z = pang_bits(w[2], nz0.z); p0.w = pang_bits(w[3], nz0.w);
            p1.x = pang_bits(w[4], nz1.x); p1.y = pang_bits(w[5], nz1.y);
            p1.z = pang_bits(w[6], nz1.z); p1.w = pang_bits(w[7], nz1.w);
            *(uint4*)&g_pang[o]     = p0;
            *(uint4*)&g_pang[o + 4] = p1;
        }
    }

    // Pass 2 — direct tile (bj, bi): adj = v; pang alongside (coalesced)
#pragma unroll
    for (int r = 0; r < 8; ++r) {
        size_t o = (size_t)(bj * 128 + ty * 8 + r) * N_NODES + bi * 128 + tx * 8;
        float4 nz0 = *(const float4*)&noise[o];
        float4 nz1 = *(const float4*)&noise[o + 4];
        *(float4*)&out[o]     = make_float4(B_[r][0], B_[r][1], B_[r][2], B_[r][3]);
        *(float4*)&out[o + 4] = make_float4(B_[r][4], B_[r][5], B_[r][6], B_[r][7]);
        uint4 p0, p1;
        p0.x = pang_bits(B_[r][0], nz0.x); p0.y = pang_bits(B_[r][1], nz0.y);
        p0.z = pang_bits(B_[r][2], nz0.z); p0.w = pang_bits(B_[r][3], nz0.w);
        p1.x = pang_bits(B_[r][4], nz1.x); p1.y = pang_bits(B_[r][5], nz1.y);
        p1.z = pang_bits(B_[r][6], nz1.z); p1.w = pang_bits(B_[r][7], nz1.w);
        *(uint4*)&g_pang[o]     = p0;
        *(uint4*)&g_pang[o + 4] = p1;
    }
}

// ---------------------------------------------------------------------------
// Kernel 3: per-row exact top-k, radix select on g_pang (one 256MB stream),
//   jax tie-break; scatter-reads only the selected adj values from out,
//   then streams the masked row back to out.
// ---------------------------------------------------------------------------
__global__ __launch_bounds__(256) void topk_mask(
    float* __restrict__ out, const int* __restrict__ kptr)
{
    __shared__ int whist[8][256];
    __shared__ int hbin[256];
    __shared__ int suf[256];
    __shared__ unsigned int s_prefix;
    __shared__ int s_r, s_e;
    __shared__ int eq_idx[128];
    __shared__ int eq_cnt;

    const int row = blockIdx.x;
    const int tid = threadIdx.x;
    const int wid = tid >> 5;
    int k = 64;
    if (kptr) k = *kptr;
    if (k < 1) k = 1;
    if (k > N_NODES) k = N_NODES;

    float* __restrict__ orow = out + (size_t)row * N_NODES;
    const uint4* p4 = (const uint4*)(g_pang + (size_t)row * N_NODES);

    unsigned pv[32];
#pragma unroll
    for (int i = 0; i < 8; ++i) {
        uint4 p = __ldg(&p4[tid + 256 * i]);
        pv[i * 4 + 0] = p.x; pv[i * 4 + 1] = p.y;
        pv[i * 4 + 2] = p.z; pv[i * 4 + 3] = p.w;
    }

    unsigned prefix = 0;
    int r = k;
#pragma unroll 1
    for (int shift = 24; shift >= 0; shift -= 8) {
        for (int i = tid; i < 8 * 256; i += 256) ((int*)whist)[i] = 0;
        __syncthreads();
        const unsigned hm = (shift == 24) ? 0u : (0xFFFFFFFFu << (shift + 8));
        int* myh = whist[wid];
#pragma unroll
        for (int i = 0; i < 32; ++i) {
            unsigned vv = pv[i];
            if ((vv & hm) == prefix) atomicAdd(&myh[(vv >> shift) & 255], 1);
        }
        __syncthreads();
        {
            int h = 0;
#pragma unroll
            for (int w = 0; w < 8; ++w) h += whist[w][tid];
            hbin[tid] = h;
            suf[tid] = h;
        }
        __syncthreads();
#pragma unroll
        for (int d = 1; d < 256; d <<= 1) {
            int tt = (tid + d < 256) ? suf[tid + d] : 0;
            __syncthreads();
            suf[tid] += tt;
            __syncthreads();
        }
        {
            int s = suf[tid];
            int snext = (tid < 255) ? suf[tid + 1] : 0;
            if (s >= r && snext < r) {
                s_prefix = prefix | ((unsigned)tid << shift);
                s_r = r - snext;
                s_e = hbin[tid];
            }
        }
        __syncthreads();
        prefix = s_prefix;
        r = s_r;
    }

    const unsigned T = prefix;
    const int e = s_e;

    if (r < e) {
        if (tid == 0) eq_cnt = 0;
        __syncthreads();
#pragma unroll
        for (int i = 0; i < 32; ++i)
            if (pv[i] == T) {
                int jj = (tid + 256 * (i >> 2)) * 4 + (i & 3);
                int p = atomicAdd(&eq_cnt, 1);
                if (p < 128) eq_idx[p] = jj;
            }
        __syncthreads();
        if (tid == 0) {
            int cnt = eq_cnt < 128 ? eq_cnt : 128;
            for (int i = 1; i < cnt; ++i) {
                int v = eq_idx[i], q = i - 1;
                while (q >= 0 && eq_idx[q] > v) { eq_idx[q + 1] = eq_idx[q]; --q; }
                eq_idx[q + 1] = v;
            }
        }
        __syncthreads();
    }

    // write masked row: scatter-read adj only for selected, zeros elsewhere
#pragma unroll
    for (int i = 0; i < 8; ++i) {
        float w[4];
#pragma unroll
        for (int c = 0; c < 4; ++c) {
            unsigned vv = pv[i * 4 + c];
            bool sel = vv > T;
            if (vv == T) {
                if (r >= e) sel = true;
                else {
                    int jj = (tid + 256 * i) * 4 + c;
                    for (int q = 0; q < r; ++q)
                        if (eq_idx[q] == jj) { sel = true; break; }
                }
            }
            w[c] = sel ? __ldg(&orow[(tid + 256 * i) * 4 + c]) : 0.0f;
        }
        ((float4*)orow)[tid + 256 * i] = make_float4(w[0], w[1], w[2], w[3]);
    }
}

// ---------------------------------------------------------------------------
extern "C" void kernel_launch(void* const* d_in, const int* in_sizes, int n_in,
                              void* d_out, int out_size)
{
    const int*   idx   = (const int*)d_in[0];
    const float* emb1  = (const float*)d_in[1];
    const float* emb2  = (const float*)d_in[2];
    const float* l1w   = (const float*)d_in[3];
    const float* l1b   = (const float*)d_in[4];
    const float* l2w   = (const float*)d_in[5];
    const float* l2b   = (const float*)d_in[6];
    const float* noise = (const float*)d_in[7];
    const int*   kptr  = (n_in > 8) ? (const int*)d_in[8] : nullptr;
    float* out = (float*)d_out;

    dim3 g1(DIM / 128, N_NODES / 128, 2);    // (4, 64, 2) both embeds — proven config
    embed_gemm<<<g1, 256>>>(emb1, emb2, l1w, l2w, l1b, l2b, idx);

    const int fused_smem = (2 * 2048 + 2 * 2048 + 16 * 1024) * (int)sizeof(float); // 96 KB
    cudaFuncSetAttribute(fused_adj_gemm,
                         cudaFuncAttributeMaxDynamicSharedMemorySize, fused_smem);
    fused_adj_gemm<<<2080, 256, fused_smem>>>(out, noise);  // adj->out, pang->g_pang

    topk_mask<<<N_NODES, 256>>>(out, kptr);

    (void)in_sizes; (void)out_size;
}

// round 15
// speedup vs baseline: 1.0240x; 1.0240x over previous
#include <cuda_runtime.h>
#include <cstdint>
#include <math.h>

#define N_NODES 8192
#define DIM     512

// scratch (device globals: no allocation allowed)
__device__ float g_n1[N_NODES * DIM];   // 16 MB
__device__ float g_n2[N_NODES * DIM];   // 16 MB

// ---------------------------------------------------------------------------
// Bit-replication of XLA fast tanh f32 (verified bitmatch rounds 3-14).
// ---------------------------------------------------------------------------
__device__ __forceinline__ float xla_tanh(float x) {
    float ax = fabsf(x);
    float xc = fminf(fmaxf(x, -7.90531110763549805f), 7.90531110763549805f);
    float x2 = __fmul_rn(xc, xc);
    float p = -2.76076847742355e-16f;
    p = fmaf(p, x2,  2.00018790482477e-13f);
    p = fmaf(p, x2, -8.60467152213735e-11f);
    p = fmaf(p, x2,  5.12229709037114e-08f);
    p = fmaf(p, x2,  1.48572235717979e-05f);
    p = fmaf(p, x2,  6.37261928875436e-04f);
    p = fmaf(p, x2,  4.89352455891786e-03f);
    float q =  1.19825839466702e-06f;
    q = fmaf(q, x2,  1.18534705686654e-04f);
    q = fmaf(q, x2,  2.26843463243900e-03f);
    q = fmaf(q, x2,  4.89352518554385e-03f);
    float r = __fdiv_rn(__fmul_rn(xc, p), q);
    return (ax < 0.0004f) ? x : r;
}

__device__ __forceinline__ float tanh3_(float x) {
    return xla_tanh(__fmul_rn(3.0f, x));
}

// ---------------------------------------------------------------------------
// 8-k slab helpers (embed kernel, proven config). Buffers: [buf*1024+k*128+row]
// ---------------------------------------------------------------------------
__device__ __forceinline__ void stage_f(
    float* sA, float* sB, int buf,
    const float4 av, const float4 bv, int lrow, int lc)
{
    float* A = sA + buf * 1024;
    float* B = sB + buf * 1024;
    A[(lc + 0) * 128 + lrow] = av.x;  A[(lc + 1) * 128 + lrow] = av.y;
    A[(lc + 2) * 128 + lrow] = av.z;  A[(lc + 3) * 128 + lrow] = av.w;
    B[(lc + 0) * 128 + lrow] = bv.x;  B[(lc + 1) * 128 + lrow] = bv.y;
    B[(lc + 2) * 128 + lrow] = bv.z;  B[(lc + 3) * 128 + lrow] = bv.w;
}

__device__ __forceinline__ void compute_pk(
    const float* sA, const float* sB, int buf,
    int TX, int TY, unsigned long long (&acc2)[8][4])
{
    const float* A = sA + buf * 1024;
    const float* B = sB + buf * 1024;
#pragma unroll
    for (int k = 0; k < 8; ++k) {
        float a[8];
        *(float4*)&a[0] = *(const float4*)&A[k * 128 + TY * 8];
        *(float4*)&a[4] = *(const float4*)&A[k * 128 + TY * 8 + 4];
        unsigned long long b2[4];
        *(float4*)&b2[0] = *(const float4*)&B[k * 128 + TX * 8];
        *(float4*)&b2[2] = *(const float4*)&B[k * 128 + TX * 8 + 4];
#pragma unroll
        for (int r = 0; r < 8; ++r) {
            unsigned long long a2;
            asm("mov.b64 %0, {%1, %1};" : "=l"(a2) : "f"(a[r]));
#pragma unroll
            for (int c2 = 0; c2 < 4; ++c2)
                asm("fma.rn.f32x2 %0, %1, %2, %0;" : "+l"(acc2[r][c2]) : "l"(a2), "l"(b2[c2]));
        }
    }
}

__device__ __forceinline__ void gemm_tile_pk(
    const float* __restrict__ Ablk, const float* __restrict__ Bblk,
    float* sA, float* sB, int lrow, int lc, int TX, int TY,
    unsigned long long (&acc2)[8][4])
{
    const float* ap = Ablk + (size_t)lrow * DIM + lc;
    const float* bp = Bblk + (size_t)lrow * DIM + lc;

    float4 av = *(const float4*)ap; ap += 8;
    float4 bv = *(const float4*)bp; bp += 8;
    stage_f(sA, sB, 0, av, bv, lrow, lc);
    __syncthreads();

#pragma unroll 1
    for (int kt = 0; kt < DIM / 8; kt += 2) {
        av = *(const float4*)ap; bv = *(const float4*)bp; ap += 8; bp += 8;
        compute_pk(sA, sB, 0, TX, TY, acc2);
        stage_f(sA, sB, 1, av, bv, lrow, lc);
        __syncthreads();
        if (kt + 2 < DIM / 8) {
            av = *(const float4*)ap; bv = *(const float4*)bp; ap += 8; bp += 8;
        }
        compute_pk(sA, sB, 1, TX, TY, acc2);
        if (kt + 2 < DIM / 8) stage_f(sA, sB, 0, av, bv, lrow, lc);
        __syncthreads();
    }
}

// ---------------------------------------------------------------------------
// Kernel 1: both embeds via blockIdx.z; 128x128 FFMA2 tiles (proven, 227us)
// ---------------------------------------------------------------------------
__global__ __launch_bounds__(256) void embed_gemm(
    const float* __restrict__ emb1, const float* __restrict__ emb2,
    const float* __restrict__ W1,   const float* __restrict__ W2,
    const float* __restrict__ b1,   const float* __restrict__ b2,
    const int* __restrict__ idx)
{
    __shared__ __align__(16) float sA[2 * 1024];
    __shared__ __align__(16) float sB[2 * 1024];

    const int which = blockIdx.z;
    const float* __restrict__ emb  = which ? emb2 : emb1;
    const float* __restrict__ W    = which ? W2   : W1;
    const float* __restrict__ bias = which ? b2   : b1;
    float* __restrict__ dst        = which ? g_n2 : g_n1;

    const int bj = blockIdx.x, bi = blockIdx.y;
    const int tid = threadIdx.x;
    const int lrow = tid >> 1, lc = (tid & 1) * 4;
    const int tx = tid & 15, ty = tid >> 4;

    unsigned long long acc2[8][4];
#pragma unroll
    for (int r = 0; r < 8; ++r)
#pragma unroll
        for (int c2 = 0; c2 < 4; ++c2) acc2[r][c2] = 0ull;

    const int arow = idx[bi * 128 + lrow];   // gather
    const float* Ablk = emb + (size_t)arow * DIM - (size_t)lrow * DIM;
    const float* Bblk = W + (size_t)(bj * 128) * DIM;

    gemm_tile_pk(Ablk, Bblk, sA, sB, lrow, lc, tx, ty, acc2);

    const int gi0 = bi * 128 + ty * 8;
    const int gj0 = bj * 128 + tx * 8;
    float bb[8];
    *(float4*)&bb[0] = *(const float4*)&bias[gj0];
    *(float4*)&bb[4] = *(const float4*)&bias[gj0 + 4];
#pragma unroll
    for (int r = 0; r < 8; ++r) {
        float accf[8];
#pragma unroll
        for (int c2 = 0; c2 < 4; ++c2) {
            float2 t = *(float2*)&acc2[r][c2];
            accf[2 * c2] = t.x; accf[2 * c2 + 1] = t.y;
        }
        float v[8];
#pragma unroll
        for (int c = 0; c < 8; ++c)
            v[c] = tanh3_(__fadd_rn(accf[c], bb[c]));
        *(float4*)&dst[(size_t)(gi0 + r) * DIM + gj0]     = make_float4(v[0], v[1], v[2], v[3]);
        *(float4*)&dst[(size_t)(gi0 + r) * DIM + gj0 + 4] = make_float4(v[4], v[5], v[6], v[7]);
    }
}

// ---------------------------------------------------------------------------
// 16-k slab helpers (fused kernel). Buffers: [buf*2048 + k*128 + row]
// ---------------------------------------------------------------------------
__device__ __forceinline__ void stage16(
    float* sA, float* sB, int buf,
    const float4 av0, const float4 av1, const float4 bv0, const float4 bv1,
    int lrow, int lc)
{
    float* A = sA + buf * 2048;
    float* B = sB + buf * 2048;
    A[(lc + 0) * 128 + lrow] = av0.x;  A[(lc + 1) * 128 + lrow] = av0.y;
    A[(lc + 2) * 128 + lrow] = av0.z;  A[(lc + 3) * 128 + lrow] = av0.w;
    A[(lc + 8) * 128 + lrow] = av1.x;  A[(lc + 9) * 128 + lrow] = av1.y;
    A[(lc +10) * 128 + lrow] = av1.z;  A[(lc +11) * 128 + lrow] = av1.w;
    B[(lc + 0) * 128 + lrow] = bv0.x;  B[(lc + 1) * 128 + lrow] = bv0.y;
    B[(lc + 2) * 128 + lrow] = bv0.z;  B[(lc + 3) * 128 + lrow] = bv0.w;
    B[(lc + 8) * 128 + lrow] = bv1.x;  B[(lc + 9) * 128 + lrow] = bv1.y;
    B[(lc +10) * 128 + lrow] = bv1.z;  B[(lc +11) * 128 + lrow] = bv1.w;
}

__device__ __forceinline__ void compute16(
    const float* sA, const float* sB, int buf,
    int TX, int TY, unsigned long long (&acc2)[8][4])
{
    const float* A = sA + buf * 2048;
    const float* B = sB + buf * 2048;
#pragma unroll
    for (int k = 0; k < 16; ++k) {
        float a[8];
        *(float4*)&a[0] = *(const float4*)&A[k * 128 + TY * 8];
        *(float4*)&a[4] = *(const float4*)&A[k * 128 + TY * 8 + 4];
        unsigned long long b2[4];
        *(float4*)&b2[0] = *(const float4*)&B[k * 128 + TX * 8];
        *(float4*)&b2[2] = *(const float4*)&B[k * 128 + TX * 8 + 4];
#pragma unroll
        for (int r = 0; r < 8; ++r) {
            unsigned long long a2;
            asm("mov.b64 %0, {%1, %1};" : "=l"(a2) : "f"(a[r]));
#pragma unroll
            for (int c2 = 0; c2 < 4; ++c2)
                asm("fma.rn.f32x2 %0, %1, %2, %0;" : "+l"(acc2[r][c2]) : "l"(a2), "l"(b2[c2]));
        }
    }
}

__device__ __forceinline__ void gemm_tile16(
    const float* __restrict__ Ablk, const float* __restrict__ Bblk,
    float* sA, float* sB, int lrow, int lc, int TX, int TY,
    unsigned long long (&acc2)[8][4])
{
    const float* ap = Ablk + (size_t)lrow * DIM + lc;
    const float* bp = Bblk + (size_t)lrow * DIM + lc;

    float4 av0 = *(const float4*)ap, av1 = *(const float4*)(ap + 8); ap += 16;
    float4 bv0 = *(const float4*)bp, bv1 = *(const float4*)(bp + 8); bp += 16;
    stage16(sA, sB, 0, av0, av1, bv0, bv1, lrow, lc);
    __syncthreads();

#pragma unroll 1
    for (int kt = 0; kt < DIM / 16; kt += 2) {
        av0 = *(const float4*)ap; av1 = *(const float4*)(ap + 8); ap += 16;
        bv0 = *(const float4*)bp; bv1 = *(const float4*)(bp + 8); bp += 16;
        compute16(sA, sB, 0, TX, TY, acc2);
        stage16(sA, sB, 1, av0, av1, bv0, bv1, lrow, lc);
        __syncthreads();
        if (kt + 2 < DIM / 16) {
            av0 = *(const float4*)ap; av1 = *(const float4*)(ap + 8); ap += 16;
            bv0 = *(const float4*)bp; bv1 = *(const float4*)(bp + 8); bp += 16;
        }
        compute16(sA, sB, 1, TX, TY, acc2);
        if (kt + 2 < DIM / 16) stage16(sA, sB, 0, av0, av1, bv0, bv1, lrow, lc);
        __syncthreads();
    }
}

// ---------------------------------------------------------------------------
// Kernel 2 (fused): triangular tiles, diagonal-last, conflict-free epilogue.
//   Phase A (roles swapped): accA(r,c) = a1(bi: tx*8+r, bj: ty*8+c) -> stash P
//   Phase B (normal):        accB(r,c) = a1(bj: ty*8+r, bi: tx*8+c)
//   v = tanh3(accB - accA^T) computed ONCE; mirror = -v, direct = v.
//   Diagonal CTAs (scheduled last): Phase B skipped via partner read from P.
// ---------------------------------------------------------------------------
__global__ __launch_bounds__(256, 2) void fused_adj_gemm(float* __restrict__ out)
{
    extern __shared__ __align__(16) float smem_dyn[];
    float* sA = smem_dyn;            // 2 * 2048 floats
    float* sB = sA + 2 * 2048;       // 2 * 2048 floats
    float* P  = sB + 2 * 2048;       // 16384 floats private stash: [e*1024 + tid*4]

    // tile decode with diagonal-last ordering
    const int t = blockIdx.x;
    int bi, bj;
    bool diag;
    if (t < 2016) {
        diag = false;
        int b = (int)((127.0 - sqrt(127.0 * 127.0 - 8.0 * (double)t)) * 0.5);
        if (b < 0) b = 0;
        if (b > 62) b = 62;
        while (b < 62 && ((b + 1) * 127 - (b + 1) * (b + 1)) / 2 <= t) ++b;
        while (b > 0 && (b * 127 - b * b) / 2 > t) --b;
        bi = b;
        bj = bi + 1 + (t - (bi * 127 - bi * bi) / 2);
    } else {
        diag = true;
        bi = bj = t - 2016;
    }

    const int tid = threadIdx.x;
    const int lrow = tid >> 1, lc = (tid & 1) * 4;
    const int tx = tid & 15, ty = tid >> 4;

    unsigned long long acc2[8][4];
#pragma unroll
    for (int r = 0; r < 8; ++r)
#pragma unroll
        for (int c2 = 0; c2 < 4; ++c2) acc2[r][c2] = 0ull;

    // Phase A, swapped roles (TX=ty, TY=tx): accA(r,c) = a1(bi: tx*8+r, bj: ty*8+c)
    gemm_tile16(g_n1 + (size_t)(bi * 128) * DIM, g_n2 + (size_t)(bj * 128) * DIM,
                sA, sB, lrow, lc, /*TX=*/ty, /*TY=*/tx, acc2);

    // stash accA: element (r,c) -> P[(2r + (c>>2))*1024 + tid*4 + (c&3)]
#pragma unroll
    for (int e = 0; e < 16; ++e) {
        const int r = e >> 1, c2 = (e & 1) * 2;
        float2 lo = *(float2*)&acc2[r][c2];
        float2 hi = *(float2*)&acc2[r][c2 + 1];
        *(float4*)&P[e * 1024 + tid * 4] = make_float4(lo.x, lo.y, hi.x, hi.y);
    }

    float B_[8][8];
    if (!diag) {
        // Phase B, normal roles: accB(r,c) = a1(bj: ty*8+r, bi: tx*8+c)
#pragma unroll
        for (int r = 0; r < 8; ++r)
#pragma unroll
            for (int c2 = 0; c2 < 4; ++c2) acc2[r][c2] = 0ull;
        gemm_tile16(g_n1 + (size_t)(bj * 128) * DIM, g_n2 + (size_t)(bi * 128) * DIM,
                    sA, sB, lrow, lc, tx, ty, acc2);
#pragma unroll
        for (int r = 0; r < 8; ++r)
#pragma unroll
            for (int c2 = 0; c2 < 4; ++c2) {
                float2 tt = *(float2*)&acc2[r][c2];
                B_[r][2 * c2] = tt.x; B_[r][2 * c2 + 1] = tt.y;
            }
        __syncthreads();
    } else {
        // diagonal: accB of thread (tx,ty) == accA of partner (ty,tx), bitwise
        __syncthreads();
        const int tid2 = (tid & 15) * 16 + (tid >> 4);
#pragma unroll
        for (int r = 0; r < 8; ++r)
#pragma unroll
            for (int c = 0; c < 8; ++c)
                B_[r][c] = P[(2 * r + (c >> 2)) * 1024 + tid2 * 4 + (c & 3)];
    }

    // tanh once, in place: B_[r][c] <- tanh3(accB(r,c) - accA(c,r))
#pragma unroll
    for (int c = 0; c < 8; ++c) {
        float rowA[8];
        *(float4*)&rowA[0] = *(const float4*)&P[(2 * c) * 1024 + tid * 4];
        *(float4*)&rowA[4] = *(const float4*)&P[(2 * c + 1) * 1024 + tid * 4];
#pragma unroll
        for (int r = 0; r < 8; ++r)
            B_[r][c] = tanh3_(__fsub_rn(B_[r][c], rowA[r]));
    }

    // Pass 1 — mirror tile (bi, bj) = -v, scattered as 32B sectors (skip diagonal)
    if (!diag) {
#pragma unroll
        for (int c = 0; c < 8; ++c) {
            size_t o = (size_t)(bi * 128 + tx * 8 + c) * N_NODES + bj * 128 + ty * 8;
            *(float4*)&out[o]     = make_float4(-B_[0][c], -B_[1][c], -B_[2][c], -B_[3][c]);
            *(float4*)&out[o + 4] = make_float4(-B_[4][c], -B_[5][c], -B_[6][c], -B_[7][c]);
        }
    }

    // Pass 2 — direct tile (bj, bi) = v, coalesced
#pragma unroll
    for (int r = 0; r < 8; ++r) {
        size_t o = (size_t)(bj * 128 + ty * 8 + r) * N_NODES + bi * 128 + tx * 8;
        *(float4*)&out[o]     = make_float4(B_[r][0], B_[r][1], B_[r][2], B_[r][3]);
        *(float4*)&out[o + 4] = make_float4(B_[r][4], B_[r][5], B_[r][6], B_[r][7]);
    }
}

// ---------------------------------------------------------------------------
// Kernel 3: per-row exact top-k mask, all-register radix select, jax tie-break.
//   Suffix scan done by warp 0 via shfl (5 barriers/pass instead of 19).
// ---------------------------------------------------------------------------
__global__ __launch_bounds__(256) void topk_mask(
    float* __restrict__ out, const float* __restrict__ noise,
    const int* __restrict__ kptr)
{
    __shared__ int whist[8][256];
    __shared__ int hbin[256];
    __shared__ int suf[256];
    __shared__ unsigned int s_prefix;
    __shared__ int s_r, s_e;
    __shared__ int eq_idx[128];
    __shared__ int eq_cnt;

    const int row = blockIdx.x;
    const int tid = threadIdx.x;
    const int wid = tid >> 5;
    const int lane = tid & 31;
    int k = 64;
    if (kptr) k = *kptr;
    if (k < 1) k = 1;
    if (k > N_NODES) k = N_NODES;

    float* __restrict__ orow = out + (size_t)row * N_NODES;
    const float4* o4 = (const float4*)orow;
    const float4* n4 = (const float4*)(noise + (size_t)row * N_NODES);

    unsigned pv[32];
    float    ov[32];
#pragma unroll
    for (int i = 0; i < 8; ++i) {
        int j4 = tid + 256 * i;
        float4 o  = __ldg(&o4[j4]);
        float4 nz = __ldg(&n4[j4]);
        ov[i * 4 + 0] = o.x; ov[i * 4 + 1] = o.y; ov[i * 4 + 2] = o.z; ov[i * 4 + 3] = o.w;
        pv[i * 4 + 0] = __float_as_uint(fabsf(__fadd_rn(o.x, __fmul_rn(0.01f, nz.x))));
        pv[i * 4 + 1] = __float_as_uint(fabsf(__fadd_rn(o.y, __fmul_rn(0.01f, nz.y))));
        pv[i * 4 + 2] = __float_as_uint(fabsf(__fadd_rn(o.z, __fmul_rn(0.01f, nz.z))));
        pv[i * 4 + 3] = __float_as_uint(fabsf(__fadd_rn(o.w, __fmul_rn(0.01f, nz.w))));
    }

    unsigned prefix = 0;
    int r = k;
#pragma unroll 1
    for (int shift = 24; shift >= 0; shift -= 8) {
        for (int i = tid; i < 8 * 256; i += 256) ((int*)whist)[i] = 0;
        __syncthreads();
        const unsigned hm = (shift == 24) ? 0u : (0xFFFFFFFFu << (shift + 8));
        int* myh = whist[wid];
#pragma unroll
        for (int i = 0; i < 32; ++i) {
            unsigned vv = pv[i];
            if ((vv & hm) == prefix) atomicAdd(&myh[(vv >> shift) & 255], 1);
        }
        __syncthreads();
        {
            int h = 0;
#pragma unroll
            for (int w = 0; w < 8; ++w) h += whist[w][tid];
            hbin[tid] = h;
        }
        __syncthreads();
        // warp-0 suffix scan over 256 bins: lane handles bins [lane*8, lane*8+8)
        if (wid == 0) {
            int v[8], s[8];
#pragma unroll
            for (int i = 0; i < 8; ++i) v[i] = hbin[lane * 8 + i];
            int run = 0;
#pragma unroll
            for (int i = 7; i >= 0; --i) { run += v[i]; s[i] = run; }
            const int total = run;
            int inc = total;   // inclusive suffix of lane totals via shfl_down
#pragma unroll
            for (int d = 1; d < 32; d <<= 1) {
                int tt = __shfl_down_sync(0xFFFFFFFFu, inc, d);
                if (lane + d < 32) inc += tt;
            }
            const int off = inc - total;   // sum of higher-lane totals
#pragma unroll
            for (int i = 0; i < 8; ++i) suf[lane * 8 + i] = s[i] + off;
        }
        __syncthreads();
        {
            int s = suf[tid];
            int snext = (tid < 255) ? suf[tid + 1] : 0;
            if (s >= r && snext < r) {
                s_prefix = prefix | ((unsigned)tid << shift);
                s_r = r - snext;
                s_e = hbin[tid];
            }
        }
        __syncthreads();
        prefix = s_prefix;
        r = s_r;
    }

    const unsigned T = prefix;
    const int e = s_e;

    if (r < e) {  // tie at threshold: keep r lowest-index equals (jax order)
        if (tid == 0) eq_cnt = 0;
        __syncthreads();
#pragma unroll
        for (int i = 0; i < 32; ++i)
            if (pv[i] == T) {
                int jj = (tid + 256 * (i >> 2)) * 4 + (i & 3);
                int p = atomicAdd(&eq_cnt, 1);
                if (p < 128) eq_idx[p] = jj;
            }
        __syncthreads();
        if (tid == 0) {
            int cnt = eq_cnt < 128 ? eq_cnt : 128;
            for (int i = 1; i < cnt; ++i) {
                int v = eq_idx[i], q = i - 1;
                while (q >= 0 && eq_idx[q] > v) { eq_idx[q + 1] = eq_idx[q]; --q; }
                eq_idx[q + 1] = v;
            }
        }
        __syncthreads();
    }

#pragma unroll
    for (int i = 0; i < 8; ++i) {
        float w[4];
#pragma unroll
        for (int c = 0; c < 4; ++c) {
            unsigned vv = pv[i * 4 + c];
            bool sel = vv > T;
            if (vv == T) {
                if (r >= e) sel = true;
                else {
                    int jj = (tid + 256 * i) * 4 + c;
                    for (int q = 0; q < r; ++q)
                        if (eq_idx[q] == jj) { sel = true; break; }
                }
            }
            w[c] = sel ? ov[i * 4 + c] : 0.0f;
        }
        ((float4*)orow)[tid + 256 * i] = make_float4(w[0], w[1], w[2], w[3]);
    }
}

// ---------------------------------------------------------------------------
extern "C" void kernel_launch(void* const* d_in, const int* in_sizes, int n_in,
                              void* d_out, int out_size)
{
    const int*   idx   = (const int*)d_in[0];
    const float* emb1  = (const float*)d_in[1];
    const float* emb2  = (const float*)d_in[2];
    const float* l1w   = (const float*)d_in[3];
    const float* l1b   = (const float*)d_in[4];
    const float* l2w   = (const float*)d_in[5];
    const float* l2b   = (const float*)d_in[6];
    const float* noise = (const float*)d_in[7];
    const int*   kptr  = (n_in > 8) ? (const int*)d_in[8] : nullptr;
    float* out = (float*)d_out;

    dim3 g1(DIM / 128, N_NODES / 128, 2);    // (4, 64, 2) both embeds — proven config
    embed_gemm<<<g1, 256>>>(emb1, emb2, l1w, l2w, l1b, l2b, idx);

    const int fused_smem = (2 * 2048 + 2 * 2048 + 16 * 1024) * (int)sizeof(float); // 96 KB
    cudaFuncSetAttribute(fused_adj_gemm,
                         cudaFuncAttributeMaxDynamicSharedMemorySize, fused_smem);
    fused_adj_gemm<<<2080, 256, fused_smem>>>(out);   // 2016 off-diag + 64 diag (last)

    topk_mask<<<N_NODES, 256>>>(out, noise, kptr);

    (void)in_sizes; (void)out_size;
}

// round 16
// speedup vs baseline: 1.0472x; 1.0227x over previous
#include <cuda_runtime.h>
#include <cstdint>
#include <math.h>

#define N_NODES 8192
#define DIM     512

// scratch (device globals: no allocation allowed)
__device__ float g_n1[N_NODES * DIM];   // 16 MB
__device__ float g_n2[N_NODES * DIM];   // 16 MB

// ---------------------------------------------------------------------------
// Bit-replication of XLA fast tanh f32 (verified bitmatch rounds 3-15).
// ---------------------------------------------------------------------------
__device__ __forceinline__ float xla_tanh(float x) {
    float ax = fabsf(x);
    float xc = fminf(fmaxf(x, -7.90531110763549805f), 7.90531110763549805f);
    float x2 = __fmul_rn(xc, xc);
    float p = -2.76076847742355e-16f;
    p = fmaf(p, x2,  2.00018790482477e-13f);
    p = fmaf(p, x2, -8.60467152213735e-11f);
    p = fmaf(p, x2,  5.12229709037114e-08f);
    p = fmaf(p, x2,  1.48572235717979e-05f);
    p = fmaf(p, x2,  6.37261928875436e-04f);
    p = fmaf(p, x2,  4.89352455891786e-03f);
    float q =  1.19825839466702e-06f;
    q = fmaf(q, x2,  1.18534705686654e-04f);
    q = fmaf(q, x2,  2.26843463243900e-03f);
    q = fmaf(q, x2,  4.89352518554385e-03f);
    float r = __fdiv_rn(__fmul_rn(xc, p), q);
    return (ax < 0.0004f) ? x : r;
}

__device__ __forceinline__ float tanh3_(float x) {
    return xla_tanh(__fmul_rn(3.0f, x));
}

// ---------------------------------------------------------------------------
// 8-k slab helpers (embed kernel, proven config). Buffers: [buf*1024+k*128+row]
// ---------------------------------------------------------------------------
__device__ __forceinline__ void stage_f(
    float* sA, float* sB, int buf,
    const float4 av, const float4 bv, int lrow, int lc)
{
    float* A = sA + buf * 1024;
    float* B = sB + buf * 1024;
    A[(lc + 0) * 128 + lrow] = av.x;  A[(lc + 1) * 128 + lrow] = av.y;
    A[(lc + 2) * 128 + lrow] = av.z;  A[(lc + 3) * 128 + lrow] = av.w;
    B[(lc + 0) * 128 + lrow] = bv.x;  B[(lc + 1) * 128 + lrow] = bv.y;
    B[(lc + 2) * 128 + lrow] = bv.z;  B[(lc + 3) * 128 + lrow] = bv.w;
}

__device__ __forceinline__ void compute_pk(
    const float* sA, const float* sB, int buf,
    int TX, int TY, unsigned long long (&acc2)[8][4])
{
    const float* A = sA + buf * 1024;
    const float* B = sB + buf * 1024;
#pragma unroll
    for (int k = 0; k < 8; ++k) {
        float a[8];
        *(float4*)&a[0] = *(const float4*)&A[k * 128 + TY * 8];
        *(float4*)&a[4] = *(const float4*)&A[k * 128 + TY * 8 + 4];
        unsigned long long b2[4];
        *(float4*)&b2[0] = *(const float4*)&B[k * 128 + TX * 8];
        *(float4*)&b2[2] = *(const float4*)&B[k * 128 + TX * 8 + 4];
#pragma unroll
        for (int r = 0; r < 8; ++r) {
            unsigned long long a2;
            asm("mov.b64 %0, {%1, %1};" : "=l"(a2) : "f"(a[r]));
#pragma unroll
            for (int c2 = 0; c2 < 4; ++c2)
                asm("fma.rn.f32x2 %0, %1, %2, %0;" : "+l"(acc2[r][c2]) : "l"(a2), "l"(b2[c2]));
        }
    }
}

__device__ __forceinline__ void gemm_tile_pk(
    const float* __restrict__ Ablk, const float* __restrict__ Bblk,
    float* sA, float* sB, int lrow, int lc, int TX, int TY,
    unsigned long long (&acc2)[8][4])
{
    const float* ap = Ablk + (size_t)lrow * DIM + lc;
    const float* bp = Bblk + (size_t)lrow * DIM + lc;

    float4 av = *(const float4*)ap; ap += 8;
    float4 bv = *(const float4*)bp; bp += 8;
    stage_f(sA, sB, 0, av, bv, lrow, lc);
    __syncthreads();

#pragma unroll 1
    for (int kt = 0; kt < DIM / 8; kt += 2) {
        av = *(const float4*)ap; bv = *(const float4*)bp; ap += 8; bp += 8;
        compute_pk(sA, sB, 0, TX, TY, acc2);
        stage_f(sA, sB, 1, av, bv, lrow, lc);
        __syncthreads();
        if (kt + 2 < DIM / 8) {
            av = *(const float4*)ap; bv = *(const float4*)bp; ap += 8; bp += 8;
        }
        compute_pk(sA, sB, 1, TX, TY, acc2);
        if (kt + 2 < DIM / 8) stage_f(sA, sB, 0, av, bv, lrow, lc);
        __syncthreads();
    }
}

// ---------------------------------------------------------------------------
// Kernel 1: both embeds via blockIdx.z; 128x128 FFMA2 tiles (proven, 227us)
// ---------------------------------------------------------------------------
__global__ __launch_bounds__(256) void embed_gemm(
    const float* __restrict__ emb1, const float* __restrict__ emb2,
    const float* __restrict__ W1,   const float* __restrict__ W2,
    const float* __restrict__ b1,   const float* __restrict__ b2,
    const int* __restrict__ idx)
{
    __shared__ __align__(16) float sA[2 * 1024];
    __shared__ __align__(16) float sB[2 * 1024];

    const int which = blockIdx.z;
    const float* __restrict__ emb  = which ? emb2 : emb1;
    const float* __restrict__ W    = which ? W2   : W1;
    const float* __restrict__ bias = which ? b2   : b1;
    float* __restrict__ dst        = which ? g_n2 : g_n1;

    const int bj = blockIdx.x, bi = blockIdx.y;
    const int tid = threadIdx.x;
    const int lrow = tid >> 1, lc = (tid & 1) * 4;
    const int tx = tid & 15, ty = tid >> 4;

    unsigned long long acc2[8][4];
#pragma unroll
    for (int r = 0; r < 8; ++r)
#pragma unroll
        for (int c2 = 0; c2 < 4; ++c2) acc2[r][c2] = 0ull;

    const int arow = idx[bi * 128 + lrow];   // gather
    const float* Ablk = emb + (size_t)arow * DIM - (size_t)lrow * DIM;
    const float* Bblk = W + (size_t)(bj * 128) * DIM;

    gemm_tile_pk(Ablk, Bblk, sA, sB, lrow, lc, tx, ty, acc2);

    const int gi0 = bi * 128 + ty * 8;
    const int gj0 = bj * 128 + tx * 8;
    float bb[8];
    *(float4*)&bb[0] = *(const float4*)&bias[gj0];
    *(float4*)&bb[4] = *(const float4*)&bias[gj0 + 4];
#pragma unroll
    for (int r = 0; r < 8; ++r) {
        float accf[8];
#pragma unroll
        for (int c2 = 0; c2 < 4; ++c2) {
            float2 t = *(float2*)&acc2[r][c2];
            accf[2 * c2] = t.x; accf[2 * c2 + 1] = t.y;
        }
        float v[8];
#pragma unroll
        for (int c = 0; c < 8; ++c)
            v[c] = tanh3_(__fadd_rn(accf[c], bb[c]));
        *(float4*)&dst[(size_t)(gi0 + r) * DIM + gj0]     = make_float4(v[0], v[1], v[2], v[3]);
        *(float4*)&dst[(size_t)(gi0 + r) * DIM + gj0 + 4] = make_float4(v[4], v[5], v[6], v[7]);
    }
}

// ---------------------------------------------------------------------------
// 16-k slab helpers (fused kernel). Buffers: [buf*2048 + k*128 + row]
// ---------------------------------------------------------------------------
__device__ __forceinline__ void stage16(
    float* sA, float* sB, int buf,
    const float4 av0, const float4 av1, const float4 bv0, const float4 bv1,
    int lrow, int lc)
{
    float* A = sA + buf * 2048;
    float* B = sB + buf * 2048;
    A[(lc + 0) * 128 + lrow] = av0.x;  A[(lc + 1) * 128 + lrow] = av0.y;
    A[(lc + 2) * 128 + lrow] = av0.z;  A[(lc + 3) * 128 + lrow] = av0.w;
    A[(lc + 8) * 128 + lrow] = av1.x;  A[(lc + 9) * 128 + lrow] = av1.y;
    A[(lc +10) * 128 + lrow] = av1.z;  A[(lc +11) * 128 + lrow] = av1.w;
    B[(lc + 0) * 128 + lrow] = bv0.x;  B[(lc + 1) * 128 + lrow] = bv0.y;
    B[(lc + 2) * 128 + lrow] = bv0.z;  B[(lc + 3) * 128 + lrow] = bv0.w;
    B[(lc + 8) * 128 + lrow] = bv1.x;  B[(lc + 9) * 128 + lrow] = bv1.y;
    B[(lc +10) * 128 + lrow] = bv1.z;  B[(lc +11) * 128 + lrow] = bv1.w;
}

__device__ __forceinline__ void compute16(
    const float* sA, const float* sB, int buf,
    int TX, int TY, unsigned long long (&acc2)[8][4])
{
    const float* A = sA + buf * 2048;
    const float* B = sB + buf * 2048;
#pragma unroll
    for (int k = 0; k < 16; ++k) {
        float a[8];
        *(float4*)&a[0] = *(const float4*)&A[k * 128 + TY * 8];
        *(float4*)&a[4] = *(const float4*)&A[k * 128 + TY * 8 + 4];
        unsigned long long b2[4];
        *(float4*)&b2[0] = *(const float4*)&B[k * 128 + TX * 8];
        *(float4*)&b2[2] = *(const float4*)&B[k * 128 + TX * 8 + 4];
#pragma unroll
        for (int r = 0; r < 8; ++r) {
            unsigned long long a2;
            asm("mov.b64 %0, {%1, %1};" : "=l"(a2) : "f"(a[r]));
#pragma unroll
            for (int c2 = 0; c2 < 4; ++c2)
                asm("fma.rn.f32x2 %0, %1, %2, %0;" : "+l"(acc2[r][c2]) : "l"(a2), "l"(b2[c2]));
        }
    }
}

__device__ __forceinline__ void gemm_tile16(
    const float* __restrict__ Ablk, const float* __restrict__ Bblk,
    float* sA, float* sB, int lrow, int lc, int TX, int TY,
    unsigned long long (&acc2)[8][4])
{
    const float* ap = Ablk + (size_t)lrow * DIM + lc;
    const float* bp = Bblk + (size_t)lrow * DIM + lc;

    float4 av0 = *(const float4*)ap, av1 = *(const float4*)(ap + 8); ap += 16;
    float4 bv0 = *(const float4*)bp, bv1 = *(const float4*)(bp + 8); bp += 16;
    stage16(sA, sB, 0, av0, av1, bv0, bv1, lrow, lc);
    __syncthreads();

#pragma unroll 1
    for (int kt = 0; kt < DIM / 16; kt += 2) {
        av0 = *(const float4*)ap; av1 = *(const float4*)(ap + 8); ap += 16;
        bv0 = *(const float4*)bp; bv1 = *(const float4*)(bp + 8); bp += 16;
        compute16(sA, sB, 0, TX, TY, acc2);
        stage16(sA, sB, 1, av0, av1, bv0, bv1, lrow, lc);
        __syncthreads();
        if (kt + 2 < DIM / 16) {
            av0 = *(const float4*)ap; av1 = *(const float4*)(ap + 8); ap += 16;
            bv0 = *(const float4*)bp; bv1 = *(const float4*)(bp + 8); bp += 16;
        }
        compute16(sA, sB, 1, TX, TY, acc2);
        if (kt + 2 < DIM / 16) stage16(sA, sB, 0, av0, av1, bv0, bv1, lrow, lc);
        __syncthreads();
    }
}

// ---------------------------------------------------------------------------
// Kernel 2 (fused): triangular tiles, diagonal-last, conflict-free epilogue.
//   Phase A (roles swapped): accA(r,c) = a1(bi: tx*8+r, bj: ty*8+c) -> stash P
//   Phase B (normal):        accB(r,c) = a1(bj: ty*8+r, bi: tx*8+c)
//   v = tanh3(accB - accA^T) computed ONCE; mirror = -v, direct = v.
//   Diagonal CTAs (scheduled last): Phase B skipped via partner read from P.
// ---------------------------------------------------------------------------
__global__ __launch_bounds__(256, 2) void fused_adj_gemm(float* __restrict__ out)
{
    extern __shared__ __align__(16) float smem_dyn[];
    float* sA = smem_dyn;            // 2 * 2048 floats
    float* sB = sA + 2 * 2048;       // 2 * 2048 floats
    float* P  = sB + 2 * 2048;       // 16384 floats private stash: [e*1024 + tid*4]

    // tile decode with diagonal-last ordering
    const int t = blockIdx.x;
    int bi, bj;
    bool diag;
    if (t < 2016) {
        diag = false;
        int b = (int)((127.0 - sqrt(127.0 * 127.0 - 8.0 * (double)t)) * 0.5);
        if (b < 0) b = 0;
        if (b > 62) b = 62;
        while (b < 62 && ((b + 1) * 127 - (b + 1) * (b + 1)) / 2 <= t) ++b;
        while (b > 0 && (b * 127 - b * b) / 2 > t) --b;
        bi = b;
        bj = bi + 1 + (t - (bi * 127 - bi * bi) / 2);
    } else {
        diag = true;
        bi = bj = t - 2016;
    }

    const int tid = threadIdx.x;
    const int lrow = tid >> 1, lc = (tid & 1) * 4;
    const int tx = tid & 15, ty = tid >> 4;

    unsigned long long acc2[8][4];
#pragma unroll
    for (int r = 0; r < 8; ++r)
#pragma unroll
        for (int c2 = 0; c2 < 4; ++c2) acc2[r][c2] = 0ull;

    // Phase A, swapped roles (TX=ty, TY=tx): accA(r,c) = a1(bi: tx*8+r, bj: ty*8+c)
    gemm_tile16(g_n1 + (size_t)(bi * 128) * DIM, g_n2 + (size_t)(bj * 128) * DIM,
                sA, sB, lrow, lc, /*TX=*/ty, /*TY=*/tx, acc2);

    // stash accA: element (r,c) -> P[(2r + (c>>2))*1024 + tid*4 + (c&3)]
#pragma unroll
    for (int e = 0; e < 16; ++e) {
        const int r = e >> 1, c2 = (e & 1) * 2;
        float2 lo = *(float2*)&acc2[r][c2];
        float2 hi = *(float2*)&acc2[r][c2 + 1];
        *(float4*)&P[e * 1024 + tid * 4] = make_float4(lo.x, lo.y, hi.x, hi.y);
    }

    float B_[8][8];
    if (!diag) {
        // Phase B, normal roles: accB(r,c) = a1(bj: ty*8+r, bi: tx*8+c)
#pragma unroll
        for (int r = 0; r < 8; ++r)
#pragma unroll
            for (int c2 = 0; c2 < 4; ++c2) acc2[r][c2] = 0ull;
        gemm_tile16(g_n1 + (size_t)(bj * 128) * DIM, g_n2 + (size_t)(bi * 128) * DIM,
                    sA, sB, lrow, lc, tx, ty, acc2);
#pragma unroll
        for (int r = 0; r < 8; ++r)
#pragma unroll
            for (int c2 = 0; c2 < 4; ++c2) {
                float2 tt = *(float2*)&acc2[r][c2];
                B_[r][2 * c2] = tt.x; B_[r][2 * c2 + 1] = tt.y;
            }
        __syncthreads();
    } else {
        // diagonal: accB of thread (tx,ty) == accA of partner (ty,tx), bitwise
        __syncthreads();
        const int tid2 = (tid & 15) * 16 + (tid >> 4);
#pragma unroll
        for (int r = 0; r < 8; ++r)
#pragma unroll
            for (int c = 0; c < 8; ++c)
                B_[r][c] = P[(2 * r + (c >> 2)) * 1024 + tid2 * 4 + (c & 3)];
    }

    // tanh once, in place: B_[r][c] <- tanh3(accB(r,c) - accA(c,r))
#pragma unroll
    for (int c = 0; c < 8; ++c) {
        float rowA[8];
        *(float4*)&rowA[0] = *(const float4*)&P[(2 * c) * 1024 + tid * 4];
        *(float4*)&rowA[4] = *(const float4*)&P[(2 * c + 1) * 1024 + tid * 4];
#pragma unroll
        for (int r = 0; r < 8; ++r)
            B_[r][c] = tanh3_(__fsub_rn(B_[r][c], rowA[r]));
    }

    // Pass 1 — mirror tile (bi, bj) = -v, scattered as 32B sectors (skip diagonal)
    if (!diag) {
#pragma unroll
        for (int c = 0; c < 8; ++c) {
            size_t o = (size_t)(bi * 128 + tx * 8 + c) * N_NODES + bj * 128 + ty * 8;
            *(float4*)&out[o]     = make_float4(-B_[0][c], -B_[1][c], -B_[2][c], -B_[3][c]);
            *(float4*)&out[o + 4] = make_float4(-B_[4][c], -B_[5][c], -B_[6][c], -B_[7][c]);
        }
    }

    // Pass 2 — direct tile (bj, bi) = v, coalesced
#pragma unroll
    for (int r = 0; r < 8; ++r) {
        size_t o = (size_t)(bj * 128 + ty * 8 + r) * N_NODES + bi * 128 + tx * 8;
        *(float4*)&out[o]     = make_float4(B_[r][0], B_[r][1], B_[r][2], B_[r][3]);
        *(float4*)&out[o + 4] = make_float4(B_[r][4], B_[r][5], B_[r][6], B_[r][7]);
    }
}

// ---------------------------------------------------------------------------
// Kernel 3: per-row exact top-k mask, all-register radix select, jax tie-break.
//   Block-wide suffix scan, ping-pong buffered: 1 barrier per step (8 total)
//   instead of 2 (16 total). All 256 threads participate (round-15 lesson:
//   do NOT serialize the scan onto one warp).
// ---------------------------------------------------------------------------
__global__ __launch_bounds__(256) void topk_mask(
    float* __restrict__ out, const float* __restrict__ noise,
    const int* __restrict__ kptr)
{
    __shared__ int whist[8][256];
    __shared__ int hbin[256];
    __shared__ int su[2][256];
    __shared__ unsigned int s_prefix;
    __shared__ int s_r, s_e;
    __shared__ int eq_idx[128];
    __shared__ int eq_cnt;

    const int row = blockIdx.x;
    const int tid = threadIdx.x;
    const int wid = tid >> 5;
    int k = 64;
    if (kptr) k = *kptr;
    if (k < 1) k = 1;
    if (k > N_NODES) k = N_NODES;

    float* __restrict__ orow = out + (size_t)row * N_NODES;
    const float4* o4 = (const float4*)orow;
    const float4* n4 = (const float4*)(noise + (size_t)row * N_NODES);

    unsigned pv[32];
    float    ov[32];
#pragma unroll
    for (int i = 0; i < 8; ++i) {
        int j4 = tid + 256 * i;
        float4 o  = __ldg(&o4[j4]);
        float4 nz = __ldg(&n4[j4]);
        ov[i * 4 + 0] = o.x; ov[i * 4 + 1] = o.y; ov[i * 4 + 2] = o.z; ov[i * 4 + 3] = o.w;
        pv[i * 4 + 0] = __float_as_uint(fabsf(__fadd_rn(o.x, __fmul_rn(0.01f, nz.x))));
        pv[i * 4 + 1] = __float_as_uint(fabsf(__fadd_rn(o.y, __fmul_rn(0.01f, nz.y))));
        pv[i * 4 + 2] = __float_as_uint(fabsf(__fadd_rn(o.z, __fmul_rn(0.01f, nz.z))));
        pv[i * 4 + 3] = __float_as_uint(fabsf(__fadd_rn(o.w, __fmul_rn(0.01f, nz.w))));
    }

    unsigned prefix = 0;
    int r = k;
#pragma unroll 1
    for (int shift = 24; shift >= 0; shift -= 8) {
        for (int i = tid; i < 8 * 256; i += 256) ((int*)whist)[i] = 0;
        __syncthreads();
        const unsigned hm = (shift == 24) ? 0u : (0xFFFFFFFFu << (shift + 8));
        int* myh = whist[wid];
#pragma unroll
        for (int i = 0; i < 32; ++i) {
            unsigned vv = pv[i];
            if ((vv & hm) == prefix) atomicAdd(&myh[(vv >> shift) & 255], 1);
        }
        __syncthreads();
        {
            int h = 0;
#pragma unroll
            for (int w = 0; w < 8; ++w) h += whist[w][tid];
            hbin[tid] = h;
            su[0][tid] = h;
        }
        __syncthreads();
        // ping-pong suffix scan: su[cur][b] accumulates sum of bins b..255
        int cur = 0;
#pragma unroll
        for (int d = 1; d < 256; d <<= 1) {
            int val = su[cur][tid] + ((tid + d < 256) ? su[cur][tid + d] : 0);
            su[cur ^ 1][tid] = val;
            __syncthreads();
            cur ^= 1;
        }
        {
            int s = su[cur][tid];
            int snext = (tid < 255) ? su[cur][tid + 1] : 0;
            if (s >= r && snext < r) {
                s_prefix = prefix | ((unsigned)tid << shift);
                s_r = r - snext;
                s_e = hbin[tid];
            }
        }
        __syncthreads();
        prefix = s_prefix;
        r = s_r;
    }

    const unsigned T = prefix;
    const int e = s_e;

    if (r < e) {  // tie at threshold: keep r lowest-index equals (jax order)
        if (tid == 0) eq_cnt = 0;
        __syncthreads();
#pragma unroll
        for (int i = 0; i < 32; ++i)
            if (pv[i] == T) {
                int jj = (tid + 256 * (i >> 2)) * 4 + (i & 3);
                int p = atomicAdd(&eq_cnt, 1);
                if (p < 128) eq_idx[p] = jj;
            }
        __syncthreads();
        if (tid == 0) {
            int cnt = eq_cnt < 128 ? eq_cnt : 128;
            for (int i = 1; i < cnt; ++i) {
                int v = eq_idx[i], q = i - 1;
                while (q >= 0 && eq_idx[q] > v) { eq_idx[q + 1] = eq_idx[q]; --q; }
                eq_idx[q + 1] = v;
            }
        }
        __syncthreads();
    }

#pragma unroll
    for (int i = 0; i < 8; ++i) {
        float w[4];
#pragma unroll
        for (int c = 0; c < 4; ++c) {
            unsigned vv = pv[i * 4 + c];
            bool sel = vv > T;
            if (vv == T) {
                if (r >= e) sel = true;
                else {
                    int jj = (tid + 256 * i) * 4 + c;
                    for (int q = 0; q < r; ++q)
                        if (eq_idx[q] == jj) { sel = true; break; }
                }
            }
            w[c] = sel ? ov[i * 4 + c] : 0.0f;
        }
        ((float4*)orow)[tid + 256 * i] = make_float4(w[0], w[1], w[2], w[3]);
    }
}

// ---------------------------------------------------------------------------
extern "C" void kernel_launch(void* const* d_in, const int* in_sizes, int n_in,
                              void* d_out, int out_size)
{
    const int*   idx   = (const int*)d_in[0];
    const float* emb1  = (const float*)d_in[1];
    const float* emb2  = (const float*)d_in[2];
    const float* l1w   = (const float*)d_in[3];
    const float* l1b   = (const float*)d_in[4];
    const float* l2w   = (const float*)d_in[5];
    const float* l2b   = (const float*)d_in[6];
    const float* noise = (const float*)d_in[7];
    const int*   kptr  = (n_in > 8) ? (const int*)d_in[8] : nullptr;
    float* out = (float*)d_out;

    dim3 g1(DIM / 128, N_NODES / 128, 2);    // (4, 64, 2) both embeds — proven config
    embed_gemm<<<g1, 256>>>(emb1, emb2, l1w, l2w, l1b, l2b, idx);

    const int fused_smem = (2 * 2048 + 2 * 2048 + 16 * 1024) * (int)sizeof(float); // 96 KB
    cudaFuncSetAttribute(fused_adj_gemm,
                         cudaFuncAttributeMaxDynamicSharedMemorySize, fused_smem);
    fused_adj_gemm<<<2080, 256, fused_smem>>>(out);   // 2016 off-diag + 64 diag (last)

    topk_mask<<<N_NODES, 256>>>(out, noise, kptr);

    (void)in_sizes; (void)out_size;
}